// round 1
// baseline (speedup 1.0000x reference)
#include <cuda_runtime.h>
#include <cuda_bf16.h>

// Problem constants
#define V_N   16000
#define L_N   12
#define K_N   512     // known units
#define M_N   512     // LOST units
#define D_N   128     // embedding dim

// ---------------------------------------------------------------------------
// Scratch (device globals; no allocation allowed in kernel_launch)
// ---------------------------------------------------------------------------
__device__ float g_lost [M_N * D_N];          // lost_unit_emb [M, D]
__device__ float g_lostT[D_N * M_N];          // transposed    [D, M]
__device__ float g_wT   [2][3][D_N * D_N];    // conv weights transposed: [which][t][i*128+o]
__device__ float g_C    [2][3][K_N * D_N];    // C[t][k][o] = sum_i emb[k][i] * w[o][i][t]
__device__ float g_T    [2][3][(K_N + 1) * M_N]; // tables; row K_N = sentinel zeros
__device__ float g_bias [2][M_N];             // bias·lost[m]
__device__ float g_ulp  [K_N * M_N];          // unit_log_probs [K, M]

// ---------------------------------------------------------------------------
// Block reduction over 512 threads (16 warps), two values at once.
// sh must have >= 34 floats.
// ---------------------------------------------------------------------------
template<bool IS_MAX>
__device__ __forceinline__ void blockReduce2(float &a, float &b, float *sh) {
    #pragma unroll
    for (int o = 16; o; o >>= 1) {
        float ta = __shfl_xor_sync(0xffffffffu, a, o);
        float tb = __shfl_xor_sync(0xffffffffu, b, o);
        if (IS_MAX) { a = fmaxf(a, ta); b = fmaxf(b, tb); }
        else        { a += ta;          b += tb;          }
    }
    int w = threadIdx.x >> 5;
    if ((threadIdx.x & 31) == 0) { sh[w] = a; sh[16 + w] = b; }
    __syncthreads();
    if (threadIdx.x < 32) {
        float x = sh[threadIdx.x];           // lanes 0-15: a partials, 16-31: b partials
        #pragma unroll
        for (int o = 8; o; o >>= 1) {
            float t = __shfl_xor_sync(0xffffffffu, x, o);
            x = IS_MAX ? fmaxf(x, t) : x + t;
        }
        if ((threadIdx.x & 15) == 0) sh[32 + (threadIdx.x >> 4)] = x;
    }
    __syncthreads();
    a = sh[32]; b = sh[33];
    __syncthreads();   // guard smem reuse by next reduction
}

// ---------------------------------------------------------------------------
// 1) lost[m][d] = sum_k aligner[m][k] * emb[k][d]        grid=512, block=128
// ---------------------------------------------------------------------------
__global__ void k_lost(const float* __restrict__ emb, const float* __restrict__ aligner) {
    int m = blockIdx.x, d = threadIdx.x;
    __shared__ float a_sm[K_N];
    for (int i = d; i < K_N; i += 128) a_sm[i] = aligner[m * K_N + i];
    __syncthreads();
    float acc = 0.f;
    for (int k = 0; k < K_N; k++) acc += a_sm[k] * emb[k * D_N + d];
    g_lost[m * D_N + d] = acc;
}

// 2) transpose lost -> lostT                             grid=512, block=128
__global__ void k_lostT() {
    int m = blockIdx.x, d = threadIdx.x;
    g_lostT[d * M_N + m] = g_lost[m * D_N + d];
}

// 3) transpose conv weights: wT[which][t][i*128+o]       grid=(128,3,2), block=128
__global__ void k_wT(const float* __restrict__ conv_w, const float* __restrict__ ins_w) {
    int i = blockIdx.x, t = blockIdx.y, which = blockIdx.z;
    int o = threadIdx.x;
    const float* w = which ? ins_w : conv_w;
    g_wT[which][t][i * D_N + o] = w[(o * D_N + i) * 3 + t];
}

// 4) bias_dot[which][m] = lost[m] . conv_b               grid=2, block=512
__global__ void k_bias(const float* __restrict__ conv_b, const float* __restrict__ ins_b) {
    int which = blockIdx.x, m = threadIdx.x;
    __shared__ float bs[D_N];
    if (m < D_N) bs[m] = which ? ins_b[m] : conv_b[m];
    __syncthreads();
    float acc = 0.f;
    for (int d = 0; d < D_N; d++) acc += g_lost[m * D_N + d] * bs[d];
    g_bias[which][m] = acc;
}

// 5) C[which][t][k][o] = sum_i emb[k][i]*wT[t][i][o]     grid=(64,3,2), block=128 (8 k per block)
__global__ void k_C(const float* __restrict__ emb) {
    int kb = blockIdx.x * 8, t = blockIdx.y, which = blockIdx.z;
    int o  = threadIdx.x;
    __shared__ float e_sm[8][D_N];
    for (int i = threadIdx.x; i < 8 * D_N; i += 128)
        e_sm[i >> 7][i & 127] = emb[kb * D_N + i];
    __syncthreads();
    float acc[8] = {0.f,0.f,0.f,0.f,0.f,0.f,0.f,0.f};
    const float* wT = g_wT[which][t];
    for (int i = 0; i < D_N; i++) {
        float w = wT[i * D_N + o];
        #pragma unroll
        for (int r = 0; r < 8; r++) acc[r] += e_sm[r][i] * w;
    }
    #pragma unroll
    for (int r = 0; r < 8; r++) g_C[which][t][(kb + r) * D_N + o] = acc[r];
}

// 6) T[which][t][k][m] = C[which][t][k] . lost[m]        grid=(64,3,2), block=512 (8 k per block)
__global__ void k_T() {
    int kb = blockIdx.x * 8, t = blockIdx.y, which = blockIdx.z;
    int m  = threadIdx.x;
    __shared__ float c_sm[8][D_N];
    for (int i = threadIdx.x; i < 8 * D_N; i += 512)
        c_sm[i >> 7][i & 127] = g_C[which][t][kb * D_N + i];
    __syncthreads();
    float acc[8] = {0.f,0.f,0.f,0.f,0.f,0.f,0.f,0.f};
    for (int d = 0; d < D_N; d++) {
        float lv = g_lostT[d * M_N + m];
        #pragma unroll
        for (int r = 0; r < 8; r++) acc[r] += c_sm[r][d] * lv;
    }
    #pragma unroll
    for (int r = 0; r < 8; r++) g_T[which][t][(kb + r) * M_N + m] = acc[r];
}

// 7) zero sentinel rows (k = K_N)                        grid=(3,2), block=512
__global__ void k_zero() {
    g_T[blockIdx.y][blockIdx.x][K_N * M_N + threadIdx.x] = 0.f;
}

// 8) unit_log_probs + alignment output                   grid=512, block=512
__global__ void __launch_bounds__(512) k_ulp(const float* __restrict__ emb,
                                             float* __restrict__ out_align) {
    int k = blockIdx.x, m = threadIdx.x;
    __shared__ float e_sm[D_N];
    __shared__ float sh[34];
    if (m < D_N) e_sm[m] = emb[k * D_N + m];
    __syncthreads();
    float acc = 0.f;
    for (int d = 0; d < D_N; d++) acc += e_sm[d] * g_lostT[d * M_N + m];
    float mx = acc, dummy = acc;
    blockReduce2<true>(mx, dummy, sh);
    float e = __expf(acc - mx);
    float s = e; dummy = e;
    blockReduce2<false>(s, dummy, sh);
    float lp = acc - mx - __logf(s);
    g_ulp[k * M_N + m]    = lp;
    out_align[k * M_N + m] = __expf(lp);
}

// ---------------------------------------------------------------------------
// 9) Main kernel: one block per vocab word v, one thread per m (512).
//    Per l: gather 3 table rows (sub) + 3 (ins) + 1 ulp row, two paired
//    block softmaxes, stream out sub & ins.
// ---------------------------------------------------------------------------
__global__ void __launch_bounds__(512) k_main(const int* __restrict__ ids,
                                              const int* __restrict__ lens,
                                              float* __restrict__ out_sub,
                                              float* __restrict__ out_ins) {
    int v = blockIdx.x;
    int m = threadIdx.x;
    __shared__ int   s_ids[L_N];
    __shared__ int   s_keff[L_N + 2];   // with sentinels at both ends
    __shared__ float sh[34];

    if (m < L_N) {
        int id  = ids[v * L_N + m];
        int len = lens[v];
        s_ids[m]      = id;
        s_keff[m + 1] = (m < len) ? id : K_N;   // masked positions -> zero row
    }
    if (m == 0) { s_keff[0] = K_N; s_keff[L_N + 1] = K_N; }

    float bsub = g_bias[0][m];
    float bins = g_bias[1][m];
    const float* __restrict__ Ts0 = g_T[0][0];
    const float* __restrict__ Ts1 = g_T[0][1];
    const float* __restrict__ Ts2 = g_T[0][2];
    const float* __restrict__ Ti0 = g_T[1][0];
    const float* __restrict__ Ti1 = g_T[1][1];
    const float* __restrict__ Ti2 = g_T[1][2];
    __syncthreads();

    for (int l = 0; l < L_N; l++) {
        int a = s_keff[l], b = s_keff[l + 1], c = s_keff[l + 2];
        float slog = bsub + Ts0[a * M_N + m] + Ts1[b * M_N + m] + Ts2[c * M_N + m];
        float ilog = bins + Ti0[a * M_N + m] + Ti1[b * M_N + m] + Ti2[c * M_N + m];

        float mxs = slog, mxi = ilog;
        blockReduce2<true>(mxs, mxi, sh);
        float es = __expf(slog - mxs);
        float ei = __expf(ilog - mxi);
        float ss = es, si = ei;
        blockReduce2<false>(ss, si, sh);

        float slp = slog - mxs - __logf(ss);
        float ilp = ilog - mxi - __logf(si);
        float glp = g_ulp[s_ids[l] * M_N + m];

        size_t off = ((size_t)(v * L_N + l)) * M_N + m;
        out_sub[off] = -0.5f * (slp + glp);        // cw = 0.5 exactly
        out_ins[off] = 3.5f - 0.5f * ilp;          // INS_DEL_COST - cw*ilp
    }
}

// ---------------------------------------------------------------------------
extern "C" void kernel_launch(void* const* d_in, const int* in_sizes, int n_in,
                              void* d_out, int out_size) {
    const float* emb     = (const float*)d_in[0];   // known_unit_emb   [512,128]
    const float* aligner = (const float*)d_in[1];   // unit_aligner_w   [512,512]
    const float* conv_w  = (const float*)d_in[2];   // [128,128,3]
    const float* conv_b  = (const float*)d_in[3];   // [128]
    const float* ins_w   = (const float*)d_in[4];   // [128,128,3]
    const float* ins_b   = (const float*)d_in[5];   // [128]
    const int*   ids     = (const int*)d_in[6];     // [16000,12]
    const int*   lens    = (const int*)d_in[7];     // [16000]

    float* out       = (float*)d_out;
    size_t big       = (size_t)V_N * L_N * M_N;     // 98,304,000
    float* out_sub   = out;
    float* out_ins   = out + big;
    float* out_align = out + 2 * big;

    k_lost <<<512, 128>>>(emb, aligner);
    k_lostT<<<512, 128>>>();
    k_wT   <<<dim3(128, 3, 2), 128>>>(conv_w, ins_w);
    k_bias <<<2, 512>>>(conv_b, ins_b);
    k_C    <<<dim3(64, 3, 2), 128>>>(emb);
    k_T    <<<dim3(64, 3, 2), 512>>>();
    k_zero <<<dim3(3, 2), 512>>>();
    k_ulp  <<<512, 512>>>(emb, out_align);
    k_main <<<V_N, 512>>>(ids, lens, out_sub, out_ins);
}

// round 2
// speedup vs baseline: 2.0669x; 2.0669x over previous
#include <cuda_runtime.h>
#include <cuda_bf16.h>

#define V_N   16000
#define L_N   12
#define K_N   512
#define M_N   512
#define D_N   128

// ---------------------------------------------------------------------------
// Scratch (device globals)
// ---------------------------------------------------------------------------
__device__ float g_lost [M_N * D_N];            // lost_unit_emb [M, D]
__device__ float g_lostT[D_N * M_N];            // [D, M]
__device__ float g_T    [2][3][(K_N + 1) * M_N]; // tables; row K_N = zeros
__device__ float g_bias [2][M_N];               // bias . lost[m]
__device__ float g_ulp  [K_N * M_N];            // unit_log_probs [K, M]

// ---------------------------------------------------------------------------
// 1) lost + lostT + bias in one kernel.  grid=512 (m), block=128 (d)
// ---------------------------------------------------------------------------
__global__ void __launch_bounds__(128) k_pre(const float* __restrict__ emb,
                                             const float* __restrict__ aligner,
                                             const float* __restrict__ conv_b,
                                             const float* __restrict__ ins_b) {
    int m = blockIdx.x, d = threadIdx.x;
    __shared__ float a_sm[K_N];
    __shared__ float red[8];
    for (int i = d; i < K_N; i += 128) a_sm[i] = aligner[m * K_N + i];
    __syncthreads();
    float acc = 0.f;
    #pragma unroll 4
    for (int k = 0; k < K_N; k++) acc += a_sm[k] * emb[k * D_N + d];
    g_lost [m * D_N + d] = acc;
    g_lostT[d * M_N + m] = acc;

    float pb = acc * conv_b[d];
    float pi = acc * ins_b[d];
    #pragma unroll
    for (int o = 16; o; o >>= 1) {
        pb += __shfl_xor_sync(0xffffffffu, pb, o);
        pi += __shfl_xor_sync(0xffffffffu, pi, o);
    }
    int w = d >> 5;
    if ((d & 31) == 0) { red[w] = pb; red[4 + w] = pi; }
    __syncthreads();
    if (d == 0) g_bias[0][m] = red[0] + red[1] + red[2] + red[3];
    if (d == 1) g_bias[1][m] = red[4] + red[5] + red[6] + red[7];
}

// ---------------------------------------------------------------------------
// 2) fused C+T: T[which][t][k][m] = (emb[k] @ w_t^T) . lost[m]
//    grid=(64,3,2) (8 k-rows per block), block=512
// ---------------------------------------------------------------------------
__global__ void __launch_bounds__(512) k_CT(const float* __restrict__ emb,
                                            const float* __restrict__ conv_w,
                                            const float* __restrict__ ins_w) {
    int kb = blockIdx.x * 8, t = blockIdx.y, which = blockIdx.z;
    int tid = threadIdx.x;
    __shared__ float e_sm[8][D_N];       // emb rows
    __shared__ float c_sm[8][D_N];       // conv output rows
    __shared__ float w_sm[32][D_N + 1];  // padded chunk of w^T

    const float* __restrict__ w = which ? ins_w : conv_w;

    for (int idx = tid; idx < 8 * D_N; idx += 512)
        e_sm[idx >> 7][idx & 127] = emb[kb * D_N + idx];

    // sentinel zero row (once, by the kb==0 blocks)
    if (blockIdx.x == 0) g_T[which][t][K_N * M_N + tid] = 0.f;

    int o  = tid & 127;         // output channel
    int rr = tid >> 7;          // 0..3 -> rows rr*2, rr*2+1
    float c0 = 0.f, c1 = 0.f;
    for (int ib = 0; ib < D_N; ib += 32) {
        __syncthreads();
        // stage w^T chunk: w_sm[i][oo] = w[(oo*128 + ib+i)*3 + t]
        for (int idx = tid; idx < 32 * D_N; idx += 512) {
            int i = idx & 31, oo = idx >> 5;
            w_sm[i][oo] = w[(oo * D_N + ib + i) * 3 + t];
        }
        __syncthreads();
        #pragma unroll
        for (int i = 0; i < 32; i++) {
            float wv = w_sm[i][o];
            c0 += e_sm[rr * 2    ][ib + i] * wv;
            c1 += e_sm[rr * 2 + 1][ib + i] * wv;
        }
    }
    c_sm[rr * 2    ][o] = c0;
    c_sm[rr * 2 + 1][o] = c1;
    __syncthreads();

    // phase T: m = tid
    int m = tid;
    float tac[8] = {0.f,0.f,0.f,0.f,0.f,0.f,0.f,0.f};
    for (int d = 0; d < D_N; d++) {
        float lv = g_lostT[d * M_N + m];
        #pragma unroll
        for (int r = 0; r < 8; r++) tac[r] += c_sm[r][d] * lv;
    }
    #pragma unroll
    for (int r = 0; r < 8; r++) g_T[which][t][(kb + r) * M_N + m] = tac[r];
}

// ---------------------------------------------------------------------------
// 3) unit_log_probs + alignment.  grid=512 (k), block=512 (m)
// ---------------------------------------------------------------------------
__global__ void __launch_bounds__(512) k_ulp(const float* __restrict__ emb,
                                             float* __restrict__ out_align) {
    int k = blockIdx.x, m = threadIdx.x;
    __shared__ float e_sm[D_N];
    __shared__ float sh[18];
    if (m < D_N) e_sm[m] = emb[k * D_N + m];
    __syncthreads();
    float acc = 0.f;
    #pragma unroll 4
    for (int d = 0; d < D_N; d++) acc += e_sm[d] * g_lostT[d * M_N + m];

    // block max
    float mx = acc;
    #pragma unroll
    for (int o = 16; o; o >>= 1) mx = fmaxf(mx, __shfl_xor_sync(0xffffffffu, mx, o));
    int w = m >> 5;
    if ((m & 31) == 0) sh[w] = mx;
    __syncthreads();
    if (m < 32) {
        float x = (m < 16) ? sh[m] : -3.4e38f;
        #pragma unroll
        for (int o = 8; o; o >>= 1) x = fmaxf(x, __shfl_xor_sync(0xffffffffu, x, o));
        if (m == 0) sh[16] = x;
    }
    __syncthreads();
    mx = sh[16];
    float e = __expf(acc - mx);
    float s = e;
    #pragma unroll
    for (int o = 16; o; o >>= 1) s += __shfl_xor_sync(0xffffffffu, s, o);
    __syncthreads();
    if ((m & 31) == 0) sh[w] = s;
    __syncthreads();
    if (m < 32) {
        float x = (m < 16) ? sh[m] : 0.f;
        #pragma unroll
        for (int o = 8; o; o >>= 1) x += __shfl_xor_sync(0xffffffffu, x, o);
        if (m == 0) sh[17] = x;
    }
    __syncthreads();
    float lp = acc - mx - __logf(sh[17]);
    g_ulp[k * M_N + m]     = lp;
    out_align[k * M_N + m] = __expf(lp);
}

// ---------------------------------------------------------------------------
// 4) Main kernel: one block per v (384 thr), one WARP per l. Barrier-free loop.
// ---------------------------------------------------------------------------
__global__ void __launch_bounds__(384) k_main(const int* __restrict__ ids,
                                              const int* __restrict__ lens,
                                              float* __restrict__ out_sub,
                                              float* __restrict__ out_ins) {
    int v    = blockIdx.x;
    int tid  = threadIdx.x;
    int lane = tid & 31;
    int l    = tid >> 5;            // warp id = position l (0..11)
    __shared__ int s_ids[L_N];
    __shared__ int s_keff[L_N + 2];

    if (tid < L_N) {
        int id  = ids[v * L_N + tid];
        int len = lens[v];
        s_ids[tid]      = id;
        s_keff[tid + 1] = (tid < len) ? id : K_N;
    }
    if (tid == 0) { s_keff[0] = K_N; s_keff[L_N + 1] = K_N; }
    __syncthreads();

    int a = s_keff[l], b = s_keff[l + 1], c = s_keff[l + 2];
    int id = s_ids[l];

    const float4* Ts0 = (const float4*)(g_T[0][0] + a * M_N);
    const float4* Ts1 = (const float4*)(g_T[0][1] + b * M_N);
    const float4* Ts2 = (const float4*)(g_T[0][2] + c * M_N);
    const float4* Ti0 = (const float4*)(g_T[1][0] + a * M_N);
    const float4* Ti1 = (const float4*)(g_T[1][1] + b * M_N);
    const float4* Ti2 = (const float4*)(g_T[1][2] + c * M_N);
    const float4* Bs  = (const float4*)(g_bias[0]);
    const float4* Bi  = (const float4*)(g_bias[1]);
    const float4* Up  = (const float4*)(g_ulp + id * M_N);

    float4 slog[4], ilog[4];
    float mxs = -3.4e38f, mxi = -3.4e38f;
    #pragma unroll
    for (int i = 0; i < 4; i++) {
        int idx = i * 32 + lane;
        float4 s0 = Ts0[idx], s1 = Ts1[idx], s2 = Ts2[idx], bs = Bs[idx];
        float4 i0 = Ti0[idx], i1 = Ti1[idx], i2 = Ti2[idx], bi = Bi[idx];
        float4 sl, il;
        sl.x = bs.x + s0.x + s1.x + s2.x;  il.x = bi.x + i0.x + i1.x + i2.x;
        sl.y = bs.y + s0.y + s1.y + s2.y;  il.y = bi.y + i0.y + i1.y + i2.y;
        sl.z = bs.z + s0.z + s1.z + s2.z;  il.z = bi.z + i0.z + i1.z + i2.z;
        sl.w = bs.w + s0.w + s1.w + s2.w;  il.w = bi.w + i0.w + i1.w + i2.w;
        slog[i] = sl; ilog[i] = il;
        mxs = fmaxf(mxs, fmaxf(fmaxf(sl.x, sl.y), fmaxf(sl.z, sl.w)));
        mxi = fmaxf(mxi, fmaxf(fmaxf(il.x, il.y), fmaxf(il.z, il.w)));
    }
    #pragma unroll
    for (int o = 16; o; o >>= 1) {
        mxs = fmaxf(mxs, __shfl_xor_sync(0xffffffffu, mxs, o));
        mxi = fmaxf(mxi, __shfl_xor_sync(0xffffffffu, mxi, o));
    }

    float ss = 0.f, si = 0.f;
    #pragma unroll
    for (int i = 0; i < 4; i++) {
        float4 sl = slog[i], il = ilog[i];
        ss += __expf(sl.x - mxs) + __expf(sl.y - mxs) +
              __expf(sl.z - mxs) + __expf(sl.w - mxs);
        si += __expf(il.x - mxi) + __expf(il.y - mxi) +
              __expf(il.z - mxi) + __expf(il.w - mxi);
    }
    #pragma unroll
    for (int o = 16; o; o >>= 1) {
        ss += __shfl_xor_sync(0xffffffffu, ss, o);
        si += __shfl_xor_sync(0xffffffffu, si, o);
    }
    float cs = mxs + __logf(ss);   // log-sum-exp offsets
    float ci = mxi + __logf(si);

    float4* Os = (float4*)(out_sub + ((size_t)(v * L_N + l)) * M_N);
    float4* Oi = (float4*)(out_ins + ((size_t)(v * L_N + l)) * M_N);
    #pragma unroll
    for (int i = 0; i < 4; i++) {
        int idx = i * 32 + lane;
        float4 g  = Up[idx];
        float4 sl = slog[i], il = ilog[i];
        float4 os, oi;
        os.x = -0.5f * ((sl.x - cs) + g.x);  oi.x = 3.5f - 0.5f * (il.x - ci);
        os.y = -0.5f * ((sl.y - cs) + g.y);  oi.y = 3.5f - 0.5f * (il.y - ci);
        os.z = -0.5f * ((sl.z - cs) + g.z);  oi.z = 3.5f - 0.5f * (il.z - ci);
        os.w = -0.5f * ((sl.w - cs) + g.w);  oi.w = 3.5f - 0.5f * (il.w - ci);
        Os[idx] = os;
        Oi[idx] = oi;
    }
}

// ---------------------------------------------------------------------------
extern "C" void kernel_launch(void* const* d_in, const int* in_sizes, int n_in,
                              void* d_out, int out_size) {
    const float* emb     = (const float*)d_in[0];
    const float* aligner = (const float*)d_in[1];
    const float* conv_w  = (const float*)d_in[2];
    const float* conv_b  = (const float*)d_in[3];
    const float* ins_w   = (const float*)d_in[4];
    const float* ins_b   = (const float*)d_in[5];
    const int*   ids     = (const int*)d_in[6];
    const int*   lens    = (const int*)d_in[7];

    float* out       = (float*)d_out;
    size_t big       = (size_t)V_N * L_N * M_N;
    float* out_sub   = out;
    float* out_ins   = out + big;
    float* out_align = out + 2 * big;

    k_pre <<<512, 128>>>(emb, aligner, conv_b, ins_b);
    k_CT  <<<dim3(64, 3, 2), 512>>>(emb, conv_w, ins_w);
    k_ulp <<<512, 512>>>(emb, out_align);
    k_main<<<V_N, 384>>>(ids, lens, out_sub, out_ins);
}